// round 4
// baseline (speedup 1.0000x reference)
#include <cuda_runtime.h>
#include <math.h>

#define BB 16
#define SS 1024
#define DD 1024
#define HH 16
#define DH 64

// Device scratch (no allocations allowed).
__device__ float g_q[BB * HH * SS * DH];   // pre-scaled by 0.125, tf32-rounded
__device__ float g_k[BB * HH * SS * DH];   // tf32-rounded
__device__ float g_v[BB * HH * SS * DH];   // tf32-rounded
__device__ float g_x[BB * SS * DD];        // tf32-rounded copy of X
__device__ float g_w[3 * DD * DD];         // tf32-rounded copies of Wq,Wk,Wv

// ---------------------------------------------------------------------------
__device__ __forceinline__ float to_tf32(float x) {
    float r;
    asm("cvt.rna.tf32.f32 %0, %1;" : "=f"(r) : "f"(x));
    return r;
}

__device__ __forceinline__ void mma_tf32(float* d, const unsigned* a, const unsigned* b) {
    asm volatile(
        "mma.sync.aligned.m16n8k8.row.col.f32.tf32.tf32.f32 "
        "{%0,%1,%2,%3},{%4,%5,%6,%7},{%8,%9},{%0,%1,%2,%3};"
        : "+f"(d[0]), "+f"(d[1]), "+f"(d[2]), "+f"(d[3])
        : "r"(a[0]), "r"(a[1]), "r"(a[2]), "r"(a[3]), "r"(b[0]), "r"(b[1]));
}

__device__ __forceinline__ unsigned smem_u32(const void* p) {
    return (unsigned)__cvta_generic_to_shared(p);
}

__device__ __forceinline__ void cp16(unsigned dst, const void* src) {
    asm volatile("cp.async.cg.shared.global [%0], [%1], 16;" :: "r"(dst), "l"(src));
}
__device__ __forceinline__ void cp_commit() {
    asm volatile("cp.async.commit_group;");
}
template <int N>
__device__ __forceinline__ void cp_wait() {
    asm volatile("cp.async.wait_group %0;" :: "n"(N));
}

// ---------------------------------------------------------------------------
// Pre-pass: tf32-round a buffer (float4).
// ---------------------------------------------------------------------------
__global__ void round_copy(float* __restrict__ dst, const float* __restrict__ src, int n4)
{
    int i = blockIdx.x * blockDim.x + threadIdx.x;
    if (i < n4) {
        float4 v = ((const float4*)src)[i];
        v.x = to_tf32(v.x); v.y = to_tf32(v.y); v.z = to_tf32(v.z); v.w = to_tf32(v.w);
        ((float4*)dst)[i] = v;
    }
}

// ---------------------------------------------------------------------------
// Fused QKV GEMM: Y = (X @ W^T + b) * scale, tf32-rounded, head-split store.
// grid (24, 128): wsel = bx>>3, n0 = (bx&7)*128. BM=BN=128, BK=32,
// 256 threads (8 warps 4x2), warp tile 32x64, cp.async double buffer.
// ---------------------------------------------------------------------------
__global__ __launch_bounds__(256)
void qkv_gemm(const float* __restrict__ bq, const float* __restrict__ bk,
              const float* __restrict__ bv)
{
    extern __shared__ float sm[];
    float* sbuf[2][2];
    sbuf[0][0] = sm;         sbuf[0][1] = sm + 4608;
    sbuf[1][0] = sm + 9216;  sbuf[1][1] = sm + 13824;

    const int tid  = threadIdx.x;
    const int lane = tid & 31;
    const int warp = tid >> 5;
    const int bx   = blockIdx.x;
    const int wsel = bx >> 3;
    const int n0   = (bx & 7) * 128;
    const int m0   = blockIdx.y * 128;

    const float* __restrict__ Wm   = g_w + (size_t)wsel * DD * DD;
    const float* __restrict__ bias = (wsel == 0) ? bq : (wsel == 1) ? bk : bv;
    float* __restrict__ Y = (wsel == 0) ? g_q : (wsel == 1) ? g_k : g_v;
    const float scale = (wsel == 0) ? 0.125f : 1.0f;

    const int wm = (warp & 3) * 32;
    const int wn = (warp >> 2) * 64;
    const int r4 = lane >> 2;
    const int c4 = lane & 3;

    const int prow = tid >> 1;
    const int pcb  = (tid & 1) * 16;
    const float* srcA = g_x + (size_t)(m0 + prow) * DD + pcb;
    const float* srcB = Wm  + (size_t)(n0 + prow) * DD + pcb;

    float acc[2][8][4];
    #pragma unroll
    for (int i = 0; i < 2; i++)
        #pragma unroll
        for (int j = 0; j < 8; j++)
            #pragma unroll
            for (int c = 0; c < 4; c++) acc[i][j][c] = 0.0f;

    {
        unsigned dA = smem_u32(sbuf[0][0] + prow * 36 + pcb);
        unsigned dB = smem_u32(sbuf[0][1] + prow * 36 + pcb);
        #pragma unroll
        for (int i = 0; i < 4; i++) {
            cp16(dA + i * 16, srcA + i * 4);
            cp16(dB + i * 16, srcB + i * 4);
        }
        cp_commit();
    }

    for (int kt = 0; kt < 32; kt++) {
        const int cur = kt & 1;
        if (kt < 31) {
            const int k0n = (kt + 1) * 32;
            unsigned dA = smem_u32(sbuf[cur ^ 1][0] + prow * 36 + pcb);
            unsigned dB = smem_u32(sbuf[cur ^ 1][1] + prow * 36 + pcb);
            #pragma unroll
            for (int i = 0; i < 4; i++) {
                cp16(dA + i * 16, srcA + k0n + i * 4);
                cp16(dB + i * 16, srcB + k0n + i * 4);
            }
            cp_commit();
            cp_wait<1>();
        } else {
            cp_wait<0>();
        }
        __syncthreads();

        const float* cA = sbuf[cur][0];
        const float* cB = sbuf[cur][1];
        #pragma unroll
        for (int ks = 0; ks < 4; ks++) {
            const int kk = ks * 8;
            unsigned af[2][4];
            #pragma unroll
            for (int mt = 0; mt < 2; mt++) {
                const int rb = wm + mt * 16;
                af[mt][0] = __float_as_uint(cA[(rb + r4    ) * 36 + kk + c4    ]);
                af[mt][1] = __float_as_uint(cA[(rb + r4 + 8) * 36 + kk + c4    ]);
                af[mt][2] = __float_as_uint(cA[(rb + r4    ) * 36 + kk + c4 + 4]);
                af[mt][3] = __float_as_uint(cA[(rb + r4 + 8) * 36 + kk + c4 + 4]);
            }
            #pragma unroll
            for (int nt = 0; nt < 8; nt++) {
                const int cb = wn + nt * 8;
                unsigned bf[2];
                bf[0] = __float_as_uint(cB[(cb + r4) * 36 + kk + c4    ]);
                bf[1] = __float_as_uint(cB[(cb + r4) * 36 + kk + c4 + 4]);
                mma_tf32(acc[0][nt], af[0], bf);
                mma_tf32(acc[1][nt], af[1], bf);
            }
        }
        __syncthreads();
    }

    #pragma unroll
    for (int mt = 0; mt < 2; mt++) {
        const int mA = m0 + wm + mt * 16 + r4;
        const int mB = mA + 8;
        const int bA = mA >> 10, sA_ = mA & 1023;
        const int bB = mB >> 10, sB_ = mB & 1023;
        #pragma unroll
        for (int nt = 0; nt < 8; nt++) {
            const int col = n0 + wn + nt * 8 + 2 * c4;
            const int h = col >> 6, d = col & 63;
            const float b0 = bias[col], b1 = bias[col + 1];
            float2 vA = make_float2(to_tf32((acc[mt][nt][0] + b0) * scale),
                                    to_tf32((acc[mt][nt][1] + b1) * scale));
            float2 vB = make_float2(to_tf32((acc[mt][nt][2] + b0) * scale),
                                    to_tf32((acc[mt][nt][3] + b1) * scale));
            *(float2*)(Y + (((size_t)(bA * HH + h) * SS + sA_) * DH) + d) = vA;
            *(float2*)(Y + (((size_t)(bB * HH + h) * SS + sB_) * DH) + d) = vB;
        }
    }
}

// ---------------------------------------------------------------------------
// Flash attention, tf32 mma. Block = 128 thr (4 warps), 16 q-rows per warp
// (R2 tiling; ~128 regs), BC=32, Dh=64. Q fragments in registers for the
// whole loop (inputs pre-rounded/pre-scaled); K/V double-buffered cp.async.
// Dynamic smem floats: K 2*32*68, V 2*32*72, P 4*16*36  -> 45056 B
// ---------------------------------------------------------------------------
#define SK_OFF 0
#define SV_OFF (2 * 32 * 68)
#define SP_OFF (SV_OFF + 2 * 32 * 72)
#define ATTN_SMEM ((SP_OFF + 4 * 16 * 36) * 4)

__global__ __launch_bounds__(128)
void attn_kernel(float* __restrict__ out)
{
    extern __shared__ float sm[];
    float* sK[2] = { sm + SK_OFF, sm + SK_OFF + 32 * 68 };
    float* sV[2] = { sm + SV_OFF, sm + SV_OFF + 32 * 72 };

    const int tid  = threadIdx.x;
    const int lane = tid & 31;
    const int warp = tid >> 5;
    const int bh   = blockIdx.y;
    const int b    = bh >> 4;
    const int h    = bh & 15;
    const int qrow0 = blockIdx.x * 64 + warp * 16;

    const int r4 = lane >> 2;
    const int c4 = lane & 3;

    float* sPw = sm + SP_OFF + warp * (16 * 36);

    const float* __restrict__ Qb = g_q + (size_t)bh * SS * DH;
    const float* __restrict__ Kb = g_k + (size_t)bh * SS * DH;
    const float* __restrict__ Vb = g_v + (size_t)bh * SS * DH;

    // Q fragments (pre-scaled, pre-rounded) straight from gmem, kept all loop.
    unsigned qa[8][4];
    {
        const float* qA = Qb + (size_t)(qrow0 + r4) * DH;
        const float* qB = Qb + (size_t)(qrow0 + r4 + 8) * DH;
        #pragma unroll
        for (int kt = 0; kt < 8; kt++) {
            const int cc = kt * 8 + c4;
            qa[kt][0] = __float_as_uint(qA[cc]);
            qa[kt][1] = __float_as_uint(qB[cc]);
            qa[kt][2] = __float_as_uint(qA[cc + 4]);
            qa[kt][3] = __float_as_uint(qB[cc + 4]);
        }
    }

    float o[8][4];
    #pragma unroll
    for (int nt = 0; nt < 8; nt++)
        #pragma unroll
        for (int c = 0; c < 4; c++) o[nt][c] = 0.0f;
    float m0v = -INFINITY, m1v = -INFINITY;
    float l0 = 0.0f, l1 = 0.0f;

    // cp.async mapping for a 32x64 tile: row = tid>>2 (0..31), colbase=(tid&3)*16
    const int prow = tid >> 2;
    const int pcb  = (tid & 3) * 16;

    {
        const float* ks = Kb + (size_t)prow * DH + pcb;
        const float* vs = Vb + (size_t)prow * DH + pcb;
        unsigned dK = smem_u32(sK[0] + prow * 68 + pcb);
        unsigned dV = smem_u32(sV[0] + prow * 72 + pcb);
        #pragma unroll
        for (int i = 0; i < 4; i++) {
            cp16(dK + i * 16, ks + i * 4);
            cp16(dV + i * 16, vs + i * 4);
        }
        cp_commit();
    }

    for (int t = 0; t < 32; t++) {
        const int cur = t & 1;
        if (t < 31) {
            const size_t roff = (size_t)((t + 1) * 32 + prow) * DH + pcb;
            const float* ks = Kb + roff;
            const float* vs = Vb + roff;
            unsigned dK = smem_u32(sK[cur ^ 1] + prow * 68 + pcb);
            unsigned dV = smem_u32(sV[cur ^ 1] + prow * 72 + pcb);
            #pragma unroll
            for (int i = 0; i < 4; i++) {
                cp16(dK + i * 16, ks + i * 4);
                cp16(dV + i * 16, vs + i * 4);
            }
            cp_commit();
            cp_wait<1>();
        } else {
            cp_wait<0>();
        }
        __syncthreads();

        const float* cK = sK[cur];
        const float* cV = sV[cur];

        // S = Q @ K^T : 4 kv n-tiles x 8 k-steps
        float s[4][4];
        #pragma unroll
        for (int nt = 0; nt < 4; nt++) {
            #pragma unroll
            for (int c = 0; c < 4; c++) s[nt][c] = 0.0f;
            #pragma unroll
            for (int kt = 0; kt < 8; kt++) {
                unsigned bf[2];
                bf[0] = __float_as_uint(cK[(nt * 8 + r4) * 68 + kt * 8 + c4    ]);
                bf[1] = __float_as_uint(cK[(nt * 8 + r4) * 68 + kt * 8 + c4 + 4]);
                mma_tf32(s[nt], qa[kt], bf);
            }
        }

        // online softmax
        float tm0 = -INFINITY, tm1 = -INFINITY;
        #pragma unroll
        for (int nt = 0; nt < 4; nt++) {
            tm0 = fmaxf(tm0, fmaxf(s[nt][0], s[nt][1]));
            tm1 = fmaxf(tm1, fmaxf(s[nt][2], s[nt][3]));
        }
        tm0 = fmaxf(tm0, __shfl_xor_sync(0xffffffffu, tm0, 1));
        tm0 = fmaxf(tm0, __shfl_xor_sync(0xffffffffu, tm0, 2));
        tm1 = fmaxf(tm1, __shfl_xor_sync(0xffffffffu, tm1, 1));
        tm1 = fmaxf(tm1, __shfl_xor_sync(0xffffffffu, tm1, 2));

        const float mn0 = fmaxf(m0v, tm0);
        const float mn1 = fmaxf(m1v, tm1);
        const float sc0 = __expf(m0v - mn0);
        const float sc1 = __expf(m1v - mn1);
        m0v = mn0; m1v = mn1;

        float ps0 = 0.0f, ps1 = 0.0f;
        #pragma unroll
        for (int nt = 0; nt < 4; nt++) {
            s[nt][0] = __expf(s[nt][0] - mn0);
            s[nt][1] = __expf(s[nt][1] - mn0);
            s[nt][2] = __expf(s[nt][2] - mn1);
            s[nt][3] = __expf(s[nt][3] - mn1);
            ps0 += s[nt][0] + s[nt][1];
            ps1 += s[nt][2] + s[nt][3];
        }
        ps0 += __shfl_xor_sync(0xffffffffu, ps0, 1);
        ps0 += __shfl_xor_sync(0xffffffffu, ps0, 2);
        ps1 += __shfl_xor_sync(0xffffffffu, ps1, 1);
        ps1 += __shfl_xor_sync(0xffffffffu, ps1, 2);
        l0 = l0 * sc0 + ps0;
        l1 = l1 * sc1 + ps1;

        #pragma unroll
        for (int nt = 0; nt < 8; nt++) {
            o[nt][0] *= sc0; o[nt][1] *= sc0;
            o[nt][2] *= sc1; o[nt][3] *= sc1;
        }

        // P -> warp-private smem (tf32 rounded), reload as A fragments
        #pragma unroll
        for (int nt = 0; nt < 4; nt++) {
            float2 pA = make_float2(to_tf32(s[nt][0]), to_tf32(s[nt][1]));
            float2 pB = make_float2(to_tf32(s[nt][2]), to_tf32(s[nt][3]));
            *(float2*)&sPw[(r4    ) * 36 + nt * 8 + 2 * c4] = pA;
            *(float2*)&sPw[(r4 + 8) * 36 + nt * 8 + 2 * c4] = pB;
        }
        __syncwarp();

        unsigned pa[4][4];
        #pragma unroll
        for (int kt = 0; kt < 4; kt++) {
            pa[kt][0] = __float_as_uint(sPw[(r4    ) * 36 + kt * 8 + c4    ]);
            pa[kt][1] = __float_as_uint(sPw[(r4 + 8) * 36 + kt * 8 + c4    ]);
            pa[kt][2] = __float_as_uint(sPw[(r4    ) * 36 + kt * 8 + c4 + 4]);
            pa[kt][3] = __float_as_uint(sPw[(r4 + 8) * 36 + kt * 8 + c4 + 4]);
        }

        // O += P @ V
        #pragma unroll
        for (int nt = 0; nt < 8; nt++) {
            #pragma unroll
            for (int kt = 0; kt < 4; kt++) {
                unsigned bf[2];
                bf[0] = __float_as_uint(cV[(kt * 8 + c4    ) * 72 + nt * 8 + r4]);
                bf[1] = __float_as_uint(cV[(kt * 8 + c4 + 4) * 72 + nt * 8 + r4]);
                mma_tf32(o[nt], pa[kt], bf);
            }
        }
        __syncthreads();
    }

    const float inv0 = 1.0f / l0;
    const float inv1 = 1.0f / l1;
    const int rA = qrow0 + r4;
    const int rB = rA + 8;
    float* oA = out + ((size_t)(b * SS + rA)) * DD + h * DH;
    float* oB = out + ((size_t)(b * SS + rB)) * DD + h * DH;
    #pragma unroll
    for (int nt = 0; nt < 8; nt++) {
        const int d = nt * 8 + 2 * c4;
        *(float2*)(oA + d) = make_float2(o[nt][0] * inv0, o[nt][1] * inv0);
        *(float2*)(oB + d) = make_float2(o[nt][2] * inv1, o[nt][3] * inv1);
    }
}

// ---------------------------------------------------------------------------
extern "C" void kernel_launch(void* const* d_in, const int* in_sizes, int n_in,
                              void* d_out, int out_size)
{
    const float* x  = (const float*)d_in[0];
    const float* Wq = (const float*)d_in[1];
    const float* bq = (const float*)d_in[2];
    const float* Wk = (const float*)d_in[3];
    const float* bk = (const float*)d_in[4];
    const float* Wv = (const float*)d_in[5];
    const float* bv = (const float*)d_in[6];
    float* out = (float*)d_out;

    cudaFuncSetAttribute(qkv_gemm, cudaFuncAttributeMaxDynamicSharedMemorySize, 18432 * 4);
    cudaFuncSetAttribute(attn_kernel, cudaFuncAttributeMaxDynamicSharedMemorySize, ATTN_SMEM);

    float* gx; cudaGetSymbolAddress((void**)&gx, g_x);
    float* gw; cudaGetSymbolAddress((void**)&gw, g_w);

    round_copy<<<(BB * SS * DD / 4 + 255) / 256, 256>>>(gx, x, BB * SS * DD / 4);
    round_copy<<<(DD * DD / 4 + 255) / 256, 256>>>(gw,               Wq, DD * DD / 4);
    round_copy<<<(DD * DD / 4 + 255) / 256, 256>>>(gw + DD * DD,     Wk, DD * DD / 4);
    round_copy<<<(DD * DD / 4 + 255) / 256, 256>>>(gw + 2 * DD * DD, Wv, DD * DD / 4);

    dim3 gg(24, 128);
    qkv_gemm<<<gg, 256, 18432 * 4>>>(bq, bk, bv);

    dim3 ga(SS / 64, BB * HH);   // (16, 256)
    attn_kernel<<<ga, 128, ATTN_SMEM>>>(out);
}

// round 5
// speedup vs baseline: 1.3707x; 1.3707x over previous
#include <cuda_runtime.h>
#include <math.h>

#define BB 16
#define SS 1024
#define DD 1024
#define HH 16
#define DH 64

// Scratch for Q, K, V in head-split layout [B, H, S, Dh] (64 MB each).
// Q is pre-scaled by 0.125; all three are tf32-rounded by the GEMM epilogue.
__device__ float g_q[BB * HH * SS * DH];
__device__ float g_k[BB * HH * SS * DH];
__device__ float g_v[BB * HH * SS * DH];

// ---------------------------------------------------------------------------
__device__ __forceinline__ float to_tf32(float x) {
    float r;
    asm("cvt.rna.tf32.f32 %0, %1;" : "=f"(r) : "f"(x));
    return r;
}

__device__ __forceinline__ void mma_tf32(float* d, const unsigned* a, const unsigned* b) {
    asm volatile(
        "mma.sync.aligned.m16n8k8.row.col.f32.tf32.tf32.f32 "
        "{%0,%1,%2,%3},{%4,%5,%6,%7},{%8,%9},{%0,%1,%2,%3};"
        : "+f"(d[0]), "+f"(d[1]), "+f"(d[2]), "+f"(d[3])
        : "r"(a[0]), "r"(a[1]), "r"(a[2]), "r"(a[3]), "r"(b[0]), "r"(b[1]));
}

// ---------------------------------------------------------------------------
// QKV projection (R2-proven): Y = to_tf32((X @ W^T + b) * scale), head-split.
// BM=BN=128, BK=32, 256 threads (8 warps as 4x2), warp tile 32x64.
// ---------------------------------------------------------------------------
__global__ __launch_bounds__(256)
void qkv_gemm(const float* __restrict__ X, const float* __restrict__ W,
              const float* __restrict__ bias, int which)
{
    __shared__ float sa[128][36];   // [m][k]
    __shared__ float sb[128][36];   // [n][k]

    float* __restrict__ Y = (which == 0) ? g_q : (which == 1) ? g_k : g_v;
    const float scale = (which == 0) ? 0.125f : 1.0f;

    const int tid  = threadIdx.x;
    const int lane = tid & 31;
    const int warp = tid >> 5;
    const int wm   = (warp & 3) * 32;
    const int wn   = (warp >> 2) * 64;
    const int m0   = blockIdx.y * 128;
    const int n0   = blockIdx.x * 128;

    const int lr = tid >> 3;
    const int lc = (tid & 7) * 4;

    float acc[2][8][4];
    #pragma unroll
    for (int i = 0; i < 2; i++)
        #pragma unroll
        for (int j = 0; j < 8; j++)
            #pragma unroll
            for (int c = 0; c < 4; c++) acc[i][j][c] = 0.0f;

    const int r4 = lane >> 2;
    const int c4 = lane & 3;

    for (int k0 = 0; k0 < DD; k0 += 32) {
        float4 va[4], vb[4];
        #pragma unroll
        for (int i = 0; i < 4; i++) {
            va[i] = *(const float4*)(X + (size_t)(m0 + lr + 32 * i) * DD + k0 + lc);
            vb[i] = *(const float4*)(W + (size_t)(n0 + lr + 32 * i) * DD + k0 + lc);
        }
        __syncthreads();
        #pragma unroll
        for (int i = 0; i < 4; i++) {
            sa[lr + 32 * i][lc + 0] = to_tf32(va[i].x);
            sa[lr + 32 * i][lc + 1] = to_tf32(va[i].y);
            sa[lr + 32 * i][lc + 2] = to_tf32(va[i].z);
            sa[lr + 32 * i][lc + 3] = to_tf32(va[i].w);
            sb[lr + 32 * i][lc + 0] = to_tf32(vb[i].x);
            sb[lr + 32 * i][lc + 1] = to_tf32(vb[i].y);
            sb[lr + 32 * i][lc + 2] = to_tf32(vb[i].z);
            sb[lr + 32 * i][lc + 3] = to_tf32(vb[i].w);
        }
        __syncthreads();

        #pragma unroll
        for (int ks = 0; ks < 4; ks++) {
            const int kk = ks * 8;
            unsigned af[2][4];
            #pragma unroll
            for (int mt = 0; mt < 2; mt++) {
                const int rb = wm + mt * 16;
                af[mt][0] = __float_as_uint(sa[rb + r4    ][kk + c4    ]);
                af[mt][1] = __float_as_uint(sa[rb + r4 + 8][kk + c4    ]);
                af[mt][2] = __float_as_uint(sa[rb + r4    ][kk + c4 + 4]);
                af[mt][3] = __float_as_uint(sa[rb + r4 + 8][kk + c4 + 4]);
            }
            #pragma unroll
            for (int nt = 0; nt < 8; nt++) {
                const int cb = wn + nt * 8;
                unsigned bf[2];
                bf[0] = __float_as_uint(sb[cb + r4][kk + c4    ]);
                bf[1] = __float_as_uint(sb[cb + r4][kk + c4 + 4]);
                mma_tf32(acc[0][nt], af[0], bf);
                mma_tf32(acc[1][nt], af[1], bf);
            }
        }
    }

    // Epilogue: (acc + bias) * scale, tf32-rounded, head-split scatter.
    #pragma unroll
    for (int mt = 0; mt < 2; mt++) {
        const int mA = m0 + wm + mt * 16 + r4;
        const int mB = mA + 8;
        const int bA = mA >> 10, sA_ = mA & 1023;
        const int bB = mB >> 10, sB_ = mB & 1023;
        #pragma unroll
        for (int nt = 0; nt < 8; nt++) {
            const int col = n0 + wn + nt * 8 + 2 * c4;
            const int h = col >> 6, d = col & 63;
            const float b0 = bias[col], b1 = bias[col + 1];
            float2 vA = make_float2(to_tf32((acc[mt][nt][0] + b0) * scale),
                                    to_tf32((acc[mt][nt][1] + b1) * scale));
            float2 vB = make_float2(to_tf32((acc[mt][nt][2] + b0) * scale),
                                    to_tf32((acc[mt][nt][3] + b1) * scale));
            *(float2*)(Y + (((size_t)(bA * HH + h) * SS + sA_) * DH) + d) = vA;
            *(float2*)(Y + (((size_t)(bB * HH + h) * SS + sB_) * DH) + d) = vB;
        }
    }
}

// ---------------------------------------------------------------------------
// Flash attention, tf32 mma (R2 tiling). Block = 128 thr (4 warps), 16 q-rows
// per warp, BC=32, Dh=64. Inputs pre-rounded (+Q pre-scaled): tile staging is
// pure float4 copy; Q fragments come straight from gmem into registers.
// ---------------------------------------------------------------------------
__global__ __launch_bounds__(128)
void attn_kernel(float* __restrict__ out)
{
    __shared__ float sk[32][68];
    __shared__ float sv[32][72];
    __shared__ float sp[4][16][36];

    const int tid  = threadIdx.x;
    const int lane = tid & 31;
    const int warp = tid >> 5;
    const int bh   = blockIdx.y;
    const int b    = bh >> 4;
    const int h    = bh & 15;
    const int qrow0 = blockIdx.x * 64 + warp * 16;

    const int r4 = lane >> 2;
    const int c4 = lane & 3;

    const float* __restrict__ Qb = g_q + (size_t)bh * SS * DH;
    const float* __restrict__ Kb = g_k + (size_t)bh * SS * DH;
    const float* __restrict__ Vb = g_v + (size_t)bh * SS * DH;

    // Q fragments (pre-scaled, pre-rounded) straight from gmem, kept all loop.
    unsigned qa[8][4];
    {
        const float* qA = Qb + (size_t)(qrow0 + r4) * DH;
        const float* qB = Qb + (size_t)(qrow0 + r4 + 8) * DH;
        #pragma unroll
        for (int kt = 0; kt < 8; kt++) {
            const int cc = kt * 8 + c4;
            qa[kt][0] = __float_as_uint(qA[cc]);
            qa[kt][1] = __float_as_uint(qB[cc]);
            qa[kt][2] = __float_as_uint(qA[cc + 4]);
            qa[kt][3] = __float_as_uint(qB[cc + 4]);
        }
    }

    float o[8][4];
    #pragma unroll
    for (int nt = 0; nt < 8; nt++)
        #pragma unroll
        for (int c = 0; c < 4; c++) o[nt][c] = 0.0f;
    float m0v = -INFINITY, m1v = -INFINITY;
    float l0 = 0.0f, l1 = 0.0f;

    for (int t0 = 0; t0 < SS; t0 += 32) {
        __syncthreads();
        // cooperative float4 tile copy: 32 rows x 16 float4 each of K and V
        #pragma unroll
        for (int i = 0; i < 4; i++) {
            const int idx = tid + i * 128;          // 0..511
            const int row = idx >> 4;               // 0..31
            const int cc  = (idx & 15) * 4;
            float4 kt4 = *(const float4*)(Kb + (size_t)(t0 + row) * DH + cc);
            float4 vt4 = *(const float4*)(Vb + (size_t)(t0 + row) * DH + cc);
            *(float4*)&sk[row][cc] = kt4;
            *(float4*)&sv[row][cc] = vt4;
        }
        __syncthreads();

        // S = Q @ K^T : 4 kv n-tiles x 8 k-steps
        float s[4][4];
        #pragma unroll
        for (int nt = 0; nt < 4; nt++) {
            #pragma unroll
            for (int c = 0; c < 4; c++) s[nt][c] = 0.0f;
            #pragma unroll
            for (int kt = 0; kt < 8; kt++) {
                unsigned bf[2];
                bf[0] = __float_as_uint(sk[nt * 8 + r4][kt * 8 + c4    ]);
                bf[1] = __float_as_uint(sk[nt * 8 + r4][kt * 8 + c4 + 4]);
                mma_tf32(s[nt], qa[kt], bf);
            }
        }

        // online softmax
        float tm0 = -INFINITY, tm1 = -INFINITY;
        #pragma unroll
        for (int nt = 0; nt < 4; nt++) {
            tm0 = fmaxf(tm0, fmaxf(s[nt][0], s[nt][1]));
            tm1 = fmaxf(tm1, fmaxf(s[nt][2], s[nt][3]));
        }
        tm0 = fmaxf(tm0, __shfl_xor_sync(0xffffffffu, tm0, 1));
        tm0 = fmaxf(tm0, __shfl_xor_sync(0xffffffffu, tm0, 2));
        tm1 = fmaxf(tm1, __shfl_xor_sync(0xffffffffu, tm1, 1));
        tm1 = fmaxf(tm1, __shfl_xor_sync(0xffffffffu, tm1, 2));

        const float mn0 = fmaxf(m0v, tm0);
        const float mn1 = fmaxf(m1v, tm1);
        const float sc0 = __expf(m0v - mn0);
        const float sc1 = __expf(m1v - mn1);
        m0v = mn0; m1v = mn1;

        float ps0 = 0.0f, ps1 = 0.0f;
        #pragma unroll
        for (int nt = 0; nt < 4; nt++) {
            s[nt][0] = __expf(s[nt][0] - mn0);
            s[nt][1] = __expf(s[nt][1] - mn0);
            s[nt][2] = __expf(s[nt][2] - mn1);
            s[nt][3] = __expf(s[nt][3] - mn1);
            ps0 += s[nt][0] + s[nt][1];
            ps1 += s[nt][2] + s[nt][3];
        }
        ps0 += __shfl_xor_sync(0xffffffffu, ps0, 1);
        ps0 += __shfl_xor_sync(0xffffffffu, ps0, 2);
        ps1 += __shfl_xor_sync(0xffffffffu, ps1, 1);
        ps1 += __shfl_xor_sync(0xffffffffu, ps1, 2);
        l0 = l0 * sc0 + ps0;
        l1 = l1 * sc1 + ps1;

        #pragma unroll
        for (int nt = 0; nt < 8; nt++) {
            o[nt][0] *= sc0; o[nt][1] *= sc0;
            o[nt][2] *= sc1; o[nt][3] *= sc1;
        }

        // P -> warp-private smem (tf32 rounded), reload as A fragments
        #pragma unroll
        for (int nt = 0; nt < 4; nt++) {
            float2 pA = make_float2(to_tf32(s[nt][0]), to_tf32(s[nt][1]));
            float2 pB = make_float2(to_tf32(s[nt][2]), to_tf32(s[nt][3]));
            *(float2*)&sp[warp][r4    ][nt * 8 + 2 * c4] = pA;
            *(float2*)&sp[warp][r4 + 8][nt * 8 + 2 * c4] = pB;
        }
        __syncwarp();

        unsigned pa[4][4];
        #pragma unroll
        for (int kt = 0; kt < 4; kt++) {
            pa[kt][0] = __float_as_uint(sp[warp][r4    ][kt * 8 + c4    ]);
            pa[kt][1] = __float_as_uint(sp[warp][r4 + 8][kt * 8 + c4    ]);
            pa[kt][2] = __float_as_uint(sp[warp][r4    ][kt * 8 + c4 + 4]);
            pa[kt][3] = __float_as_uint(sp[warp][r4 + 8][kt * 8 + c4 + 4]);
        }

        // O += P @ V
        #pragma unroll
        for (int nt = 0; nt < 8; nt++) {
            #pragma unroll
            for (int kt = 0; kt < 4; kt++) {
                unsigned bf[2];
                bf[0] = __float_as_uint(sv[kt * 8 + c4    ][nt * 8 + r4]);
                bf[1] = __float_as_uint(sv[kt * 8 + c4 + 4][nt * 8 + r4]);
                mma_tf32(o[nt], pa[kt], bf);
            }
        }
        __syncwarp();
    }

    // epilogue: normalize and store
    const float inv0 = 1.0f / l0;
    const float inv1 = 1.0f / l1;
    const int rA = qrow0 + r4;
    const int rB = rA + 8;
    float* oA = out + ((size_t)(b * SS + rA)) * DD + h * DH;
    float* oB = out + ((size_t)(b * SS + rB)) * DD + h * DH;
    #pragma unroll
    for (int nt = 0; nt < 8; nt++) {
        const int d = nt * 8 + 2 * c4;
        *(float2*)(oA + d) = make_float2(o[nt][0] * inv0, o[nt][1] * inv0);
        *(float2*)(oB + d) = make_float2(o[nt][2] * inv1, o[nt][3] * inv1);
    }
}

extern "C" void kernel_launch(void* const* d_in, const int* in_sizes, int n_in,
                              void* d_out, int out_size)
{
    const float* x  = (const float*)d_in[0];
    const float* Wq = (const float*)d_in[1];
    const float* bq = (const float*)d_in[2];
    const float* Wk = (const float*)d_in[3];
    const float* bk = (const float*)d_in[4];
    const float* Wv = (const float*)d_in[5];
    const float* bv = (const float*)d_in[6];
    float* out = (float*)d_out;

    dim3 gg(DD / 128, (BB * SS) / 128);   // (8, 128)
    qkv_gemm<<<gg, 256>>>(x, Wq, bq, 0);
    qkv_gemm<<<gg, 256>>>(x, Wk, bk, 1);
    qkv_gemm<<<gg, 256>>>(x, Wv, bv, 2);

    dim3 ga(SS / 64, BB * HH);            // (16, 256)
    attn_kernel<<<ga, 128>>>(out);
}